// round 17
// baseline (speedup 1.0000x reference)
#include <cuda_runtime.h>

// Problem constants
#define NN 1024
#define DD 64
#define RR 32
#define NB 820        // persistent grid: 820 blocks <= 6/SM * 148 SMs = 888 resident
#define NTILES 4096   // 64x64 tiles of 16x16 pairs
#define MAXT 5        // max tiles per block: ceil(4096/820)

// Accumulators / barrier state (no device allocation allowed).
// Zero-initialized at load; cleanup ticket re-zeroes after every launch, so
// each kernel_launch call (and each graph replay) starts from identical state.
__device__ double g_sum;
__device__ double g_sumsq;
__device__ unsigned long long g_cnt;
__device__ unsigned int g_arrive;
__device__ unsigned int g_release;
__device__ unsigned int g_fin;
__device__ float g_mean;
__device__ float g_invstd;

// Softmax/scale for one 4-value slice of a pair. 8-lane-group reductions.
// res in [-1,1] for nonzero entries (no overflow without max-subtraction);
// masked entries contribute e=0 exactly; all-zero rows guarded via s==0 -> 0.
__device__ __forceinline__ void out_pair(float4 m, float4 mg, float ew,
                                         float mean, float invstd,
                                         float4& o) {
    float4 g = make_float4(m.x * mg.x, m.y * mg.y, m.z * mg.z, m.w * mg.w);

    float mx = fmaxf(fmaxf(g.x, g.y), fmaxf(g.z, g.w));
    float mn = fminf(fminf(g.x, g.y), fminf(g.z, g.w));
    #pragma unroll
    for (int off = 4; off > 0; off >>= 1) {
        mx = fmaxf(mx, __shfl_xor_sync(0xffffffffu, mx, off));
        mn = fminf(mn, __shfl_xor_sync(0xffffffffu, mn, off));
    }

    const float inv2 = 2.0f / (mx - mn);   // inf if all-zero; e's selected to 0 below

    float e0 = (g.x == 0.0f) ? 0.0f : __expf(fmaf(g.x - mn, inv2, -1.0f));
    float e1 = (g.y == 0.0f) ? 0.0f : __expf(fmaf(g.y - mn, inv2, -1.0f));
    float e2 = (g.z == 0.0f) ? 0.0f : __expf(fmaf(g.z - mn, inv2, -1.0f));
    float e3 = (g.w == 0.0f) ? 0.0f : __expf(fmaf(g.w - mn, inv2, -1.0f));

    float s = (e0 + e1) + (e2 + e3);
    #pragma unroll
    for (int off = 4; off > 0; off >>= 1)
        s += __shfl_xor_sync(0xffffffffu, s, off);

    const float invs = (s > 0.0f) ? (1.0f / s) : 0.0f;

    float sig = 0.0f;
    if (ew != 0.0f)
        sig = 1.0f / (1.0f + __expf(-(ew - mean) * invstd));

    const float f = sig * invs;
    o = make_float4(e0 * m.x * f, e1 * m.y * f, e2 * m.z * f, e3 * m.w * f);
}

// One persistent kernel:
//  phase 1: per-tile ewm (2-deep pipelined dot products), results -> SMEM,
//           stats accumulated in registers, one atomicAdd triple per block.
//  barrier: ticket; last block computes mean/invstd (unbiased std, ddof=1).
//  phase 2: per-tile fused softmax/sigmoid epilogue, ewm read from SMEM.
__global__ void __launch_bounds__(256, 6)
k_fused(const float* __restrict__ grad, const float* __restrict__ rs,
        const float* __restrict__ rm, const float* __restrict__ rmg,
        float* __restrict__ out) {
    __shared__ float4 s_ewm[MAXT * 64];       // 256 ewm floats per tile
    __shared__ double s_sum[8], s_ss[8];
    __shared__ unsigned int s_cnt[8];
    __shared__ float s_stats[2];

    const int tid  = threadIdx.x;
    const int w    = tid >> 5;
    const int lane = tid & 31;
    const int pg   = lane >> 3;   // pair within 4-pair group (0..3)
    const int sub  = lane & 7;    // chunk within pair (0..7)

    float ls = 0.0f, lss = 0.0f;
    unsigned int lc = 0u;

    // ---------------- phase 1: ewm ----------------
    {
        int ltile = 0;
        for (int t = blockIdx.x; t < NTILES; t += NB, ++ltile) {
            const int i0 = (t >> 6) << 4;
            const int j0 = (t & 63) << 4;

            #pragma unroll
            for (int s = 0; s < 8; s += 2) {
                const int gA = s * 8 + w;
                const int gB = gA + 8;
                const int iA = i0 + (gA >> 2), jA = (gA & 3) << 2;
                const int iB = i0 + (gB >> 2), jB = (gB & 3) << 2;

                const float4* gaA = (const float4*)(grad + (((size_t)iA << 10) + j0 + jA + pg) * DD);
                const float4* raA = (const float4*)(rs   + (((size_t)(j0 + jA + pg) << 10) + iA) * DD);
                const float4* gaB = (const float4*)(grad + (((size_t)iB << 10) + j0 + jB + pg) * DD);
                const float4* raB = (const float4*)(rs   + (((size_t)(j0 + jB + pg) << 10) + iB) * DD);

                // issue all 8 loads up front (2-deep MLP)
                float4 Ag0 = gaA[sub];
                float4 Ag1 = gaA[sub + 8];
                float4 Ar0 = raA[sub];
                float4 Ar1 = raA[sub + 8];
                float4 Bg0 = gaB[sub];
                float4 Bg1 = gaB[sub + 8];
                float4 Br0 = raB[sub];
                float4 Br1 = raB[sub + 8];

                float accA = Ag0.x * Ar0.x + Ag0.y * Ar0.y + Ag0.z * Ar0.z + Ag0.w * Ar0.w
                           + Ag1.x * Ar1.x + Ag1.y * Ar1.y + Ag1.z * Ar1.z + Ag1.w * Ar1.w;
                accA += __shfl_xor_sync(0xffffffffu, accA, 4);
                accA += __shfl_xor_sync(0xffffffffu, accA, 2);
                accA += __shfl_xor_sync(0xffffffffu, accA, 1);

                float a0 = __shfl_sync(0xffffffffu, accA, 0);
                float a1 = __shfl_sync(0xffffffffu, accA, 8);
                float a2 = __shfl_sync(0xffffffffu, accA, 16);
                float a3 = __shfl_sync(0xffffffffu, accA, 24);
                if (lane == 0)
                    s_ewm[ltile * 64 + (gA >> 2) * 4 + (gA & 3)] = make_float4(a0, a1, a2, a3);
                if (sub == 0 && accA != 0.0f) { ls += accA; lss += accA * accA; lc += 1u; }

                float accB = Bg0.x * Br0.x + Bg0.y * Br0.y + Bg0.z * Br0.z + Bg0.w * Br0.w
                           + Bg1.x * Br1.x + Bg1.y * Br1.y + Bg1.z * Br1.z + Bg1.w * Br1.w;
                accB += __shfl_xor_sync(0xffffffffu, accB, 4);
                accB += __shfl_xor_sync(0xffffffffu, accB, 2);
                accB += __shfl_xor_sync(0xffffffffu, accB, 1);

                float b0 = __shfl_sync(0xffffffffu, accB, 0);
                float b1 = __shfl_sync(0xffffffffu, accB, 8);
                float b2 = __shfl_sync(0xffffffffu, accB, 16);
                float b3 = __shfl_sync(0xffffffffu, accB, 24);
                if (lane == 0)
                    s_ewm[ltile * 64 + (gB >> 2) * 4 + (gB & 3)] = make_float4(b0, b1, b2, b3);
                if (sub == 0 && accB != 0.0f) { ls += accB; lss += accB * accB; lc += 1u; }
            }
        }
    }

    // block-level stats reduce (each pair counted at exactly one lane)
    #pragma unroll
    for (int off = 16; off > 0; off >>= 1) {
        ls  += __shfl_xor_sync(0xffffffffu, ls, off);
        lss += __shfl_xor_sync(0xffffffffu, lss, off);
        lc  += __shfl_xor_sync(0xffffffffu, lc, off);
    }
    if (lane == 0) { s_sum[w] = (double)ls; s_ss[w] = (double)lss; s_cnt[w] = lc; }
    __syncthreads();

    // ---------------- device-wide barrier + stats ----------------
    if (tid == 0) {
        double bs = 0.0, bss = 0.0;
        unsigned int bc = 0u;
        #pragma unroll
        for (int k = 0; k < 8; ++k) { bs += s_sum[k]; bss += s_ss[k]; bc += s_cnt[k]; }
        atomicAdd(&g_sum, bs);
        atomicAdd(&g_sumsq, bss);
        atomicAdd(&g_cnt, (unsigned long long)bc);
        __threadfence();

        unsigned int ticket = atomicAdd(&g_arrive, 1u);
        if (ticket == NB - 1) {
            // all blocks' accumulator updates are visible (fence-before-arrive)
            double sum = __ldcg(&g_sum);
            double ss  = __ldcg(&g_sumsq);
            double c   = (double)__ldcg((const long long*)&g_cnt);
            double mean = sum / c;
            double var  = (ss - sum * sum / c) / (c - 1.0);
            float fm = (float)mean;
            float fi = (float)(1.0 / sqrt(var));
            g_mean   = fm;
            g_invstd = fi;
            __threadfence();
            atomicExch(&g_release, 1u);
            s_stats[0] = fm;
            s_stats[1] = fi;
        } else {
            while (atomicAdd(&g_release, 0u) == 0u) __nanosleep(128);
            s_stats[0] = __ldcg(&g_mean);
            s_stats[1] = __ldcg(&g_invstd);
        }
    }
    __syncthreads();

    const float mean   = s_stats[0];
    const float invstd = s_stats[1];

    // ---------------- phase 2: fused epilogue ----------------
    {
        int ltile = 0;
        for (int t = blockIdx.x; t < NTILES; t += NB, ++ltile) {
            const int i0 = (t >> 6) << 4;
            const int j0 = (t & 63) << 4;
            const float* ewm_t = (const float*)(s_ewm + ltile * 64);

            for (int k = 0; k < 4; ++k) {
                const int q     = k * 8 + w;      // 8-pair group id (0..31)
                const int i_loc = q >> 1;
                const int jbase = (q & 1) << 3;   // 0 or 8

                const size_t f4A = (((size_t)(i0 + i_loc) << 10) + j0 + jbase) * (RR / 4) + lane;
                const size_t f4B = f4A + 32;
                const int plA = i_loc * 16 + jbase + pg;

                // ewm from SMEM (no global traffic), then global loads (MLP)
                float ewA = ewm_t[plA];
                float ewB = ewm_t[plA + 4];
                float4 mA = __ldcs(((const float4*)rm)  + f4A);
                float4 gA = __ldcs(((const float4*)rmg) + f4A);
                float4 mB = __ldcs(((const float4*)rm)  + f4B);
                float4 gB = __ldcs(((const float4*)rmg) + f4B);

                float4 oA, oB;
                out_pair(mA, gA, ewA, mean, invstd, oA);
                out_pair(mB, gB, ewB, mean, invstd, oB);

                __stcs(((float4*)out) + f4A, oA);
                __stcs(((float4*)out) + f4B, oB);
            }
        }
    }

    // ---------------- cleanup ticket: reset state for next replay ----------------
    __syncthreads();
    if (tid == 0) {
        __threadfence();
        unsigned int ticket = atomicAdd(&g_fin, 1u);
        if (ticket == NB - 1) {
            // every block has passed the release barrier and finished phase 2;
            // no spinner can observe these resets mid-flight.
            g_sum = 0.0;
            g_sumsq = 0.0;
            g_cnt = 0ull;
            g_arrive = 0u;
            g_release = 0u;
            g_fin = 0u;
            __threadfence();
        }
    }
}

extern "C" void kernel_launch(void* const* d_in, const int* in_sizes, int n_in,
                              void* d_out, int out_size) {
    const float* rs   = (const float*)d_in[0];  // relation_stocks [N,N,D]
    const float* grad = (const float*)d_in[1];  // grad            [N,N,D]
    const float* rm   = (const float*)d_in[2];  // relation_matrix [N,N,R]
    const float* rmg  = (const float*)d_in[3];  // relation_matrix_grad [N,N,R]
    float* out = (float*)d_out;                 // [N,N,R]

    (void)in_sizes; (void)n_in; (void)out_size;

    k_fused<<<NB, 256>>>(grad, rs, rm, rmg, out);
}